// round 1
// baseline (speedup 1.0000x reference)
#include <cuda_runtime.h>

#define DIMS   256
#define BATCH  2048

// Scratch: rel^T, relT[k*BATCH + b] = x[b,k] - offsets[k]   (2 MB)
__device__ float g_relT[DIMS * BATCH];

// ---------------------------------------------------------------------------
// Kernel 1: build rel^T (coalesced writes; tiny, ~few us)
// ---------------------------------------------------------------------------
__global__ void prep_relT_kernel(const float* __restrict__ x,
                                 const float* __restrict__ offsets) {
    int idx = blockIdx.x * blockDim.x + threadIdx.x;   // 0 .. D*B-1
    int k = idx / BATCH;
    int b = idx % BATCH;
    g_relT[idx] = x[b * DIMS + k] - offsets[k];
}

// ---------------------------------------------------------------------------
// Kernel 2: out[b] = c0 + <c1, r_b> + r_b^T c2 r_b      (initializes out)
// One block handles 32 batch elements; thread t owns column j=t of c2.
// ---------------------------------------------------------------------------
__global__ void __launch_bounds__(256) low_order_kernel(
    const float* __restrict__ c0p,
    const float* __restrict__ c1,
    const float* __restrict__ c2,
    float* __restrict__ out) {

    __shared__ float rs[DIMS][33];   // padded to kill bank conflicts
    __shared__ float ssum[32];

    const int tid = threadIdx.x;     // = j
    const int b0  = blockIdx.x * 32;

    for (int idx = tid; idx < DIMS * 32; idx += 256) {
        int i  = idx >> 5;
        int bl = idx & 31;
        rs[i][bl] = g_relT[i * BATCH + b0 + bl];
    }
    if (tid < 32) ssum[tid] = 0.f;
    __syncthreads();

    float acc[32];
#pragma unroll
    for (int bl = 0; bl < 32; bl++) acc[bl] = 0.f;

    for (int i = 0; i < DIMS; i++) {
        float c2v = c2[i * DIMS + tid];          // coalesced
#pragma unroll
        for (int bl = 0; bl < 32; bl++)
            acc[bl] += c2v * rs[i][bl];          // broadcast LDS
    }

    const float c1v = c1[tid];
    for (int bl = 0; bl < 32; bl++) {
        float v = rs[tid][bl] * (c1v + acc[bl]);
#pragma unroll
        for (int o = 16; o > 0; o >>= 1)
            v += __shfl_down_sync(0xFFFFFFFFu, v, o);
        if ((tid & 31) == 0) atomicAdd(&ssum[bl], v);
    }
    __syncthreads();
    if (tid < 32) out[b0 + tid] = c0p[0] + ssum[tid];
}

// ---------------------------------------------------------------------------
// Kernel 3: fused GEMM  C[(ij),b] = c3 @ rel^T, epilogue weight r_i*r_j and
// reduce over (ij) into out[b] via atomicAdd.
//   M = 65536 (flattened (i,j)), N = 2048 (b), K = 256 (k)
//   Block tile: BM=128 x BN=64, BK=16; 256 threads; 8x4 micro-tile.
//   Since BM=128 and rows of one i-slab span 256, each block has ONE i.
// ---------------------------------------------------------------------------
#define BM 128
#define BN 64
#define BK 16

__global__ void __launch_bounds__(256) taylor3_kernel(
    const float* __restrict__ c3,
    float* __restrict__ out) {

    __shared__ float As[BK][BM];      // 8 KB, stored K-outer for vector LDS
    __shared__ float Bs[BK][BN];      // 4 KB
    __shared__ float red[16][BN];     // 4 KB

    const int tid = threadIdx.x;
    const int tm  = tid >> 4;         // 0..15  (M direction)
    const int tn  = tid & 15;         // 0..15  (N direction)
    const int m0  = blockIdx.x * BM;  // row offset into 65536
    const int b0  = blockIdx.y * BN;  // batch offset
    const int iglob = m0 >> 8;        // the single i of this block
    const int j0    = m0 & (DIMS - 1);

    float acc[8][4];
#pragma unroll
    for (int mi = 0; mi < 8; mi++)
#pragma unroll
        for (int ni = 0; ni < 4; ni++) acc[mi][ni] = 0.f;

    for (int k0 = 0; k0 < DIMS; k0 += BK) {
        // --- load A tile (128 x 16), transposed into As[k][m] ---
#pragma unroll
        for (int l = 0; l < 2; l++) {
            int t   = tid + l * 256;       // 0..511
            int row = t >> 2;              // 0..127
            int c4  = (t & 3) << 2;        // 0,4,8,12
            float4 v = *(const float4*)(c3 + (size_t)(m0 + row) * DIMS + k0 + c4);
            As[c4 + 0][row] = v.x;
            As[c4 + 1][row] = v.y;
            As[c4 + 2][row] = v.z;
            As[c4 + 3][row] = v.w;
        }
        // --- load B tile (16 x 64) from relT, coalesced ---
        {
            int row = tid >> 4;            // 0..15
            int c4  = (tid & 15) << 2;     // 0..60
            *(float4*)&Bs[row][c4] =
                *(const float4*)(g_relT + (k0 + row) * BATCH + b0 + c4);
        }
        __syncthreads();

#pragma unroll
        for (int k = 0; k < BK; k++) {
            float a[8], bb[4];
            *(float4*)&a[0] = *(const float4*)&As[k][tm * 8];
            *(float4*)&a[4] = *(const float4*)&As[k][tm * 8 + 4];
            *(float4*)&bb[0] = *(const float4*)&Bs[k][tn * 4];
#pragma unroll
            for (int mi = 0; mi < 8; mi++)
#pragma unroll
                for (int ni = 0; ni < 4; ni++)
                    acc[mi][ni] += a[mi] * bb[ni];
        }
        __syncthreads();
    }

    // --- epilogue: weight by r[b,j]*r[b,i], reduce over M within block ---
#pragma unroll
    for (int ni = 0; ni < 4; ni++) {
        int b = b0 + tn * 4 + ni;
        float ri = g_relT[iglob * BATCH + b];
        float s = 0.f;
#pragma unroll
        for (int mi = 0; mi < 8; mi++) {
            int j = j0 + tm * 8 + mi;
            s += acc[mi][ni] * g_relT[j * BATCH + b];   // L2/L1 hits (2 MB)
        }
        red[tm][tn * 4 + ni] = s * ri;
    }
    __syncthreads();

    if (tid < BN) {
        float s = 0.f;
#pragma unroll
        for (int t = 0; t < 16; t++) s += red[t][tid];
        atomicAdd(out + b0 + tid, s);
    }
}

// ---------------------------------------------------------------------------
extern "C" void kernel_launch(void* const* d_in, const int* in_sizes, int n_in,
                              void* d_out, int out_size) {
    const float* x       = (const float*)d_in[0];   // (2048, 256)
    const float* offsets = (const float*)d_in[1];   // (256,)
    const float* coeff0  = (const float*)d_in[2];   // scalar
    const float* coeff1  = (const float*)d_in[3];   // (256,)
    const float* coeff2  = (const float*)d_in[4];   // (256,256)
    const float* coeff3  = (const float*)d_in[5];   // (256,256,256)
    float* out = (float*)d_out;                     // (2048,)

    prep_relT_kernel<<<(DIMS * BATCH) / 256, 256>>>(x, offsets);
    low_order_kernel<<<BATCH / 32, 256>>>(coeff0, coeff1, coeff2, out);

    dim3 grid((DIMS * DIMS) / BM, BATCH / BN);      // (512, 32)
    taylor3_kernel<<<grid, 256>>>(coeff3, out);
}

// round 3
// speedup vs baseline: 2.0088x; 2.0088x over previous
#include <cuda_runtime.h>
#include <cstdint>

#define DIMS   256
#define BATCH  2048
#define BM     128
#define BN     128
#define BK     32

// relT[k*BATCH + b] = x[b,k] - offsets[k]   (2 MB scratch, epilogue weights)
__device__ float g_relT[DIMS * BATCH];

static __device__ __forceinline__ uint32_t f2tf32(float f) {
    uint32_t r;
    asm("cvt.rna.tf32.f32 %0, %1;" : "=r"(r) : "f"(f));
    return r;
}

#define MMA_TF32(C, A, B)                                                     \
    asm volatile(                                                             \
        "mma.sync.aligned.m16n8k8.row.col.f32.tf32.tf32.f32 "                 \
        "{%0,%1,%2,%3}, {%4,%5,%6,%7}, {%8,%9}, {%0,%1,%2,%3};"               \
        : "+f"((C)[0]), "+f"((C)[1]), "+f"((C)[2]), "+f"((C)[3])              \
        : "r"((A).x), "r"((A).y), "r"((A).z), "r"((A).w),                     \
          "r"((B).x), "r"((B).y))

// ---------------------------------------------------------------------------
__global__ void prep_relT_kernel(const float* __restrict__ x,
                                 const float* __restrict__ offsets) {
    int idx = blockIdx.x * blockDim.x + threadIdx.x;
    int k = idx / BATCH;
    int b = idx % BATCH;
    g_relT[idx] = x[b * DIMS + k] - offsets[k];
}

// out[b] = c0 + <c1, rel[b,:]>
__global__ void __launch_bounds__(256) init_out_kernel(
    const float* __restrict__ x, const float* __restrict__ offsets,
    const float* __restrict__ c0p, const float* __restrict__ c1,
    float* __restrict__ out) {
    __shared__ float ws[8];
    int b = blockIdx.x, t = threadIdx.x;
    float r = x[b * DIMS + t] - offsets[t];
    float v = r * c1[t];
#pragma unroll
    for (int o = 16; o > 0; o >>= 1) v += __shfl_down_sync(0xFFFFFFFFu, v, o);
    if ((t & 31) == 0) ws[t >> 5] = v;
    __syncthreads();
    if (t == 0) {
        float s = c0p[0];
#pragma unroll
        for (int i = 0; i < 8; i++) s += ws[i];
        out[b] = s;
    }
}

// ---------------------------------------------------------------------------
// Fused GEMM + weighted reduction on the tensor pipe (mma.sync tf32).
//   bx <  512 : rows of coeff3 (i = bx>>1, jbase = (bx&1)*128), weight r_i*r_j
//   bx >= 512 : rows of coeff2 (jbase = (bx-512)*128),          weight r_j
// SMEM tiles are stored in mma-fragment order:
//   A: idx = ((kstep*8 + msub)*32 + lane)*4 + r        (4 regs / thread)
//   B: idx = ((kstep*16 + nsub)*32 + lane)*2 + r       (2 regs / thread)
// ---------------------------------------------------------------------------
#define CHUNK_FLOATS (BM * BK)            // 4096 per operand
#define BUF_FLOATS   (2 * CHUNK_FLOATS)   // A + B
#define SMEM_FLOATS  (2 * BUF_FLOATS + BN)
#define NCHUNK       (DIMS / BK)          // 8

__global__ void __launch_bounds__(256, 2) taylor_mma_kernel(
    const float* __restrict__ x, const float* __restrict__ offsets,
    const float* __restrict__ coeff2, const float* __restrict__ coeff3,
    float* __restrict__ out) {

    extern __shared__ float smf[];
    float* sred = smf + 2 * BUF_FLOATS;

    const int tid  = threadIdx.x;
    const int wid  = tid >> 5, lane = tid & 31;
    const int warpM = wid & 3, warpN = wid >> 2;
    const int g = lane >> 2, tig = lane & 3;      // groupID, threadID_in_group
    const int bx = blockIdx.x;
    const int b0 = blockIdx.y * BN;

    const float* Ag;
    int jbase, iglob;
    if (bx < 512) { Ag = coeff3 + (size_t)bx * BM * DIMS; jbase = (bx & 1) * 128; iglob = bx >> 1; }
    else          { Ag = coeff2 + (size_t)(bx - 512) * BM * DIMS; jbase = (bx - 512) * 128; iglob = -1; }

    float acc[2][8][4];
#pragma unroll
    for (int m = 0; m < 2; m++)
#pragma unroll
        for (int n = 0; n < 8; n++)
#pragma unroll
            for (int r = 0; r < 4; r++) acc[m][n][r] = 0.f;

    float4 pa[4], pb[4];

    // ---- prefetch (LDG) a K-chunk into registers ----
    auto ldg_chunk = [&](int k0) {
#pragma unroll
        for (int it = 0; it < 4; it++) {
            int idx  = tid + it * 256;
            int row  = idx >> 3;              // 0..127
            int k4   = (idx & 7) << 2;        // 0,4,...,28
            pa[it] = *(const float4*)(Ag + (size_t)row * DIMS + k0 + k4);
            float4 xv = *(const float4*)(x + (size_t)(b0 + row) * DIMS + k0 + k4);
            float4 ov = *(const float4*)(offsets + k0 + k4);
            pb[it] = make_float4(xv.x - ov.x, xv.y - ov.y, xv.z - ov.z, xv.w - ov.w);
        }
    };

    // ---- store prefetched chunk into fragment-ordered SMEM (tf32) ----
    auto sts_chunk = [&](int buf) {
        uint32_t* As = (uint32_t*)(smf + buf * BUF_FLOATS);
        uint32_t* Bs = As + CHUNK_FLOATS;
#pragma unroll
        for (int it = 0; it < 4; it++) {
            int idx  = tid + it * 256;
            int row  = idx >> 3;
            int k4   = (idx & 7) << 2;
            int ksl  = k4 >> 3;
            // A: row = m
            {
                int msub = row >> 4, mrow = row & 15;
                int r    = ((k4 & 4) ? 2 : 0) | (mrow >> 3);
                int base = ((ksl * 8 + msub) * 32 + (mrow & 7) * 4) * 4 + r;
                As[base + 0]  = f2tf32(pa[it].x);
                As[base + 4]  = f2tf32(pa[it].y);
                As[base + 8]  = f2tf32(pa[it].z);
                As[base + 12] = f2tf32(pa[it].w);
            }
            // B: row = n (batch)
            {
                int nsub = row >> 3, ncol = row & 7;
                int r    = (k4 & 4) ? 1 : 0;
                int base = ((ksl * 16 + nsub) * 32 + ncol * 4) * 2 + r;
                Bs[base + 0] = f2tf32(pb[it].x);
                Bs[base + 2] = f2tf32(pb[it].y);
                Bs[base + 4] = f2tf32(pb[it].z);
                Bs[base + 6] = f2tf32(pb[it].w);
            }
        }
    };

    if (tid < BN) sred[tid] = 0.f;
    ldg_chunk(0);
    sts_chunk(0);
    __syncthreads();

    for (int c = 0; c < NCHUNK; ++c) {
        const int buf = c & 1;
        if (c + 1 < NCHUNK) ldg_chunk((c + 1) * BK);

        const uint32_t* As = (const uint32_t*)(smf + buf * BUF_FLOATS);
        const uint32_t* Bs = As + CHUNK_FLOATS;
#pragma unroll
        for (int ks = 0; ks < BK / 8; ++ks) {
            uint4 a0 = *(const uint4*)&As[((ks * 8 + warpM * 2 + 0) * 32 + lane) * 4];
            uint4 a1 = *(const uint4*)&As[((ks * 8 + warpM * 2 + 1) * 32 + lane) * 4];
#pragma unroll
            for (int nsl = 0; nsl < 8; ++nsl) {
                uint2 bf = *(const uint2*)&Bs[((ks * 16 + warpN * 8 + nsl) * 32 + lane) * 2];
                MMA_TF32(acc[0][nsl], a0, bf);
                MMA_TF32(acc[1][nsl], a1, bf);
            }
        }

        if (c + 1 < NCHUNK) {
            __syncthreads();          // all warps done reading buf before refill path
            sts_chunk(buf ^ 1);
            __syncthreads();
        }
    }

    // ---- epilogue: sred[col] += sum_j D[j,col] * relT[j, b0+col] ----
#pragma unroll
    for (int nsl = 0; nsl < 8; ++nsl) {
        const int coln = warpN * 64 + nsl * 8 + tig * 2;  // col within block
        float p0 = 0.f, p1 = 0.f;
#pragma unroll
        for (int msl = 0; msl < 2; ++msl) {
            int j1 = jbase + warpM * 32 + msl * 16 + g;
            const float* w = g_relT + (size_t)j1 * BATCH + b0 + coln;
            float2 wa = *(const float2*)w;
            float2 wb = *(const float2*)(w + 8 * BATCH);
            p0 += acc[msl][nsl][0] * wa.x + acc[msl][nsl][2] * wb.x;
            p1 += acc[msl][nsl][1] * wa.y + acc[msl][nsl][3] * wb.y;
        }
#pragma unroll
        for (int o = 4; o <= 16; o <<= 1) {
            p0 += __shfl_xor_sync(0xFFFFFFFFu, p0, o);
            p1 += __shfl_xor_sync(0xFFFFFFFFu, p1, o);
        }
        if (g == 0) {
            atomicAdd(&sred[coln],     p0);
            atomicAdd(&sred[coln + 1], p1);
        }
    }
    __syncthreads();

    if (tid < BN) {
        int b = b0 + tid;
        float ri = (iglob >= 0) ? g_relT[(size_t)iglob * BATCH + b] : 1.0f;
        atomicAdd(out + b, sred[tid] * ri);
    }
}

// ---------------------------------------------------------------------------
extern "C" void kernel_launch(void* const* d_in, const int* in_sizes, int n_in,
                              void* d_out, int out_size) {
    const float* x       = (const float*)d_in[0];
    const float* offsets = (const float*)d_in[1];
    const float* coeff0  = (const float*)d_in[2];
    const float* coeff1  = (const float*)d_in[3];
    const float* coeff2  = (const float*)d_in[4];
    const float* coeff3  = (const float*)d_in[5];
    float* out = (float*)d_out;

    cudaFuncSetAttribute(taylor_mma_kernel,
                         cudaFuncAttributeMaxDynamicSharedMemorySize,
                         SMEM_FLOATS * sizeof(float));

    prep_relT_kernel<<<(DIMS * BATCH) / 256, 256>>>(x, offsets);
    init_out_kernel<<<BATCH, 256>>>(x, offsets, coeff0, coeff1, out);

    dim3 grid(514, BATCH / BN);   // 512 c3 tiles + 2 c2 tiles, 16 batch tiles
    taylor_mma_kernel<<<grid, 256, SMEM_FLOATS * sizeof(float)>>>(
        x, offsets, coeff2, coeff3, out);
}

// round 4
// speedup vs baseline: 4.9715x; 2.4748x over previous
#include <cuda_runtime.h>
#include <cstdint>

#define DIMS   256
#define BATCH  2048
#define NPAIR  32896              // 256*257/2 upper-triangle pairs
#define NROWS  33280              // 260 tiles * 128 rows (pairs + c2 + c1 + pad)
#define BM     128
#define BN     128
#define KC     32
#define NCHUNK (DIMS / KC)        // 8

// ---- device scratch (allocation-free) ----
__device__ float    g_c3p[NROWS * DIMS];         // 34 MB packed+symmetrized A
__device__ uint32_t g_pairIdx[NROWS];            // (i<<16)|j per row
__device__ float    g_rel[BATCH * DIMS];         // rel, row-major [b][k]
__device__ float    g_relT[(DIMS + 1) * BATCH];  // rel^T [k][b]; row 256 = 1.0

static __device__ __forceinline__ uint32_t f2tf32(float f) {
    uint32_t r;
    asm("cvt.rna.tf32.f32 %0, %1;" : "=r"(r) : "f"(f));
    return r;
}

#define MMA_TF32(C, A0, A1, A2, A3, B0, B1)                                   \
    asm volatile(                                                             \
        "mma.sync.aligned.m16n8k8.row.col.f32.tf32.tf32.f32 "                 \
        "{%0,%1,%2,%3}, {%4,%5,%6,%7}, {%8,%9}, {%0,%1,%2,%3};"               \
        : "+f"((C)[0]), "+f"((C)[1]), "+f"((C)[2]), "+f"((C)[3])              \
        : "r"(A0), "r"(A1), "r"(A2), "r"(A3), "r"(B0), "r"(B1))

// ---------------------------------------------------------------------------
// Prep: rel (row-major) + relT (k-major, +ones row)
// ---------------------------------------------------------------------------
__global__ void prep_rel_kernel(const float* __restrict__ x,
                                const float* __restrict__ offsets) {
    int idx = blockIdx.x * blockDim.x + threadIdx.x;   // k*BATCH + b
    int k = idx / BATCH;
    int b = idx % BATCH;
    if (k < DIMS) {
        float r = x[b * DIMS + k] - offsets[k];
        g_relT[idx] = r;
        g_rel[b * DIMS + k] = r;
    } else {
        g_relT[idx] = 1.0f;    // ones row (index 256)
    }
}

__global__ void init_out_kernel(const float* __restrict__ c0p,
                                float* __restrict__ out) {
    int b = blockIdx.x * blockDim.x + threadIdx.x;
    if (b < BATCH) out[b] = c0p[0];
}

// ---------------------------------------------------------------------------
// Pack: symmetrize c3 upper triangle, append c2 rows, c1 row, zero pad.
// grid = (256 j, 258 i-slot), 64 threads copy one 256-float row.
// ---------------------------------------------------------------------------
__global__ void pack_kernel(const float* __restrict__ c3,
                            const float* __restrict__ c2,
                            const float* __restrict__ c1) {
    int j = blockIdx.x, i = blockIdx.y, t = threadIdx.x;
    int p;
    float4 v;
    uint32_t pidx;
    if (i < 256) {
        if (j < i) return;
        p = i * 256 - (i * (i - 1)) / 2 + (j - i);
        v = *(const float4*)(c3 + ((size_t)(i * 256 + j)) * DIMS + t * 4);
        if (i != j) {
            float4 w = *(const float4*)(c3 + ((size_t)(j * 256 + i)) * DIMS + t * 4);
            v.x += w.x; v.y += w.y; v.z += w.z; v.w += w.w;
        }
        pidx = ((uint32_t)i << 16) | (uint32_t)j;
    } else if (i == 256) {                       // c2 rows, weight r_j * 1
        p = NPAIR + j;
        v = *(const float4*)(c2 + (size_t)j * DIMS + t * 4);
        pidx = (256u << 16) | (uint32_t)j;
    } else {                                     // i == 257
        if (j == 0) {                            // c1 row, weight 1 * 1
            p = NPAIR + 256;
            v = *(const float4*)(c1 + t * 4);
        } else if (j < 128) {                    // zero pad rows
            p = NPAIR + 256 + j;
            v = make_float4(0.f, 0.f, 0.f, 0.f);
        } else return;
        pidx = (256u << 16) | 256u;
    }
    *(float4*)(g_c3p + (size_t)p * DIMS + t * 4) = v;
    if (t == 0) g_pairIdx[p] = pidx;
}

// ---------------------------------------------------------------------------
// Main fused GEMM: D = c3p(128 rows) @ rel^T(128 cols), weighted reduce.
// SMEM: SW128-swizzled row-major tiles (128 rows x 32 k), double buffered.
// ---------------------------------------------------------------------------
#define CHUNK_W (BM * KC)                 // 4096 words per operand chunk
#define BUF_W   (2 * CHUNK_W)             // A + B
#define SMEM_W  (2 * BUF_W + BN)          // 16512 words = 66 KB

__global__ void __launch_bounds__(256, 2) taylor_mma_kernel(
    float* __restrict__ out) {

    extern __shared__ float smf[];
    float* sred = smf + 2 * BUF_W;

    const int tid  = threadIdx.x;
    const int lane = tid & 31, wid = tid >> 5;
    const int warpM = wid & 3, warpN = wid >> 2;
    const int g = lane >> 2, tig = lane & 3;
    const int p0 = blockIdx.x * BM;
    const int b0 = blockIdx.y * BN;

    const float* Ag = g_c3p + (size_t)p0 * DIMS;
    const float* Bg = g_rel + (size_t)b0 * DIMS;

    float acc[2][8][4];
#pragma unroll
    for (int m = 0; m < 2; m++)
#pragma unroll
        for (int n = 0; n < 8; n++)
#pragma unroll
            for (int r = 0; r < 4; r++) acc[m][n][r] = 0.f;

    float4 pa[4], pb[4];

    auto ldg_chunk = [&](int k0) {
#pragma unroll
        for (int it = 0; it < 4; it++) {
            int idx = tid + it * 256;            // 0..1023
            int row = idx >> 3;                  // 0..127
            int kk  = (idx & 7) << 2;            // 0..28
            pa[it] = *(const float4*)(Ag + (size_t)row * DIMS + k0 + kk);
            pb[it] = *(const float4*)(Bg + (size_t)row * DIMS + k0 + kk);
        }
    };

    auto sts_chunk = [&](int buf) {
        char* As = (char*)(smf + buf * BUF_W);
        char* Bs = As + CHUNK_W * 4;
#pragma unroll
        for (int it = 0; it < 4; it++) {
            int idx = tid + it * 256;
            int row = idx >> 3;
            int kk  = (idx & 7) << 2;
            uint32_t bo = row * 128 + kk * 4;
            uint32_t sw = bo ^ ((bo >> 3) & 0x70);
            uint4 a = make_uint4(f2tf32(pa[it].x), f2tf32(pa[it].y),
                                 f2tf32(pa[it].z), f2tf32(pa[it].w));
            uint4 b = make_uint4(f2tf32(pb[it].x), f2tf32(pb[it].y),
                                 f2tf32(pb[it].z), f2tf32(pb[it].w));
            *(uint4*)(As + sw) = a;
            *(uint4*)(Bs + sw) = b;
        }
    };

    if (tid < BN) sred[tid] = 0.f;
    ldg_chunk(0);
    sts_chunk(0);
    __syncthreads();

    const int kxor = g << 2;                     // swizzle XOR on word k-index

    for (int c = 0; c < NCHUNK; ++c) {
        const int buf = c & 1;
        if (c + 1 < NCHUNK) ldg_chunk((c + 1) * KC);

        const uint32_t* As = (const uint32_t*)(smf + buf * BUF_W);
        const uint32_t* Bs = As + CHUNK_W;

#pragma unroll
        for (int ks = 0; ks < KC / 8; ++ks) {
            const int k0x = (ks * 8 + tig) ^ kxor;    // swizzled word-k
            const int k1x = k0x ^ 4;                  // (k+4) swizzled
            uint32_t A0[4], A1[4];
            {
                int m = warpM * 32 + g;
                A0[0] = As[m * 32 + k0x];
                A0[1] = As[(m + 8) * 32 + k0x];
                A0[2] = As[m * 32 + k1x];
                A0[3] = As[(m + 8) * 32 + k1x];
                m += 16;
                A1[0] = As[m * 32 + k0x];
                A1[1] = As[(m + 8) * 32 + k0x];
                A1[2] = As[m * 32 + k1x];
                A1[3] = As[(m + 8) * 32 + k1x];
            }
#pragma unroll
            for (int nsl = 0; nsl < 8; ++nsl) {
                int n = warpN * 64 + nsl * 8 + g;
                uint32_t B0 = Bs[n * 32 + k0x];
                uint32_t B1 = Bs[n * 32 + k1x];
                MMA_TF32(acc[0][nsl], A0[0], A0[1], A0[2], A0[3], B0, B1);
                MMA_TF32(acc[1][nsl], A1[0], A1[1], A1[2], A1[3], B0, B1);
            }
        }

        if (c + 1 < NCHUNK) {
            __syncthreads();
            sts_chunk(buf ^ 1);
            __syncthreads();
        }
    }

    // ---- epilogue: sred[col] += sum_m D[m,col] * r_i(m)[b] * r_j(m)[b] ----
    const float* wi[2][2];
    const float* wj[2][2];
#pragma unroll
    for (int msl = 0; msl < 2; ++msl)
#pragma unroll
        for (int h = 0; h < 2; ++h) {
            int rloc = warpM * 32 + msl * 16 + h * 8 + g;
            uint32_t pij = g_pairIdx[p0 + rloc];
            wi[msl][h] = g_relT + (size_t)(pij >> 16) * BATCH + b0;
            wj[msl][h] = g_relT + (size_t)(pij & 0xFFFF) * BATCH + b0;
        }

#pragma unroll
    for (int nsl = 0; nsl < 8; ++nsl) {
        const int coln = warpN * 64 + nsl * 8 + tig * 2;
        float s0 = 0.f, s1 = 0.f;
#pragma unroll
        for (int msl = 0; msl < 2; ++msl) {
            float2 a = *(const float2*)(wi[msl][0] + coln);
            float2 b = *(const float2*)(wj[msl][0] + coln);
            s0 += acc[msl][nsl][0] * a.x * b.x;
            s1 += acc[msl][nsl][1] * a.y * b.y;
            a = *(const float2*)(wi[msl][1] + coln);
            b = *(const float2*)(wj[msl][1] + coln);
            s0 += acc[msl][nsl][2] * a.x * b.x;
            s1 += acc[msl][nsl][3] * a.y * b.y;
        }
#pragma unroll
        for (int o = 4; o <= 16; o <<= 1) {
            s0 += __shfl_xor_sync(0xFFFFFFFFu, s0, o);
            s1 += __shfl_xor_sync(0xFFFFFFFFu, s1, o);
        }
        if (g == 0) {
            atomicAdd(&sred[coln],     s0);
            atomicAdd(&sred[coln + 1], s1);
        }
    }
    __syncthreads();

    if (tid < BN) atomicAdd(out + b0 + tid, sred[tid]);
}

// ---------------------------------------------------------------------------
extern "C" void kernel_launch(void* const* d_in, const int* in_sizes, int n_in,
                              void* d_out, int out_size) {
    const float* x       = (const float*)d_in[0];
    const float* offsets = (const float*)d_in[1];
    const float* coeff0  = (const float*)d_in[2];
    const float* coeff1  = (const float*)d_in[3];
    const float* coeff2  = (const float*)d_in[4];
    const float* coeff3  = (const float*)d_in[5];
    float* out = (float*)d_out;

    cudaFuncSetAttribute(taylor_mma_kernel,
                         cudaFuncAttributeMaxDynamicSharedMemorySize,
                         SMEM_W * sizeof(float));

    prep_rel_kernel<<<((DIMS + 1) * BATCH) / 256, 256>>>(x, offsets);
    init_out_kernel<<<BATCH / 256, 256>>>(coeff0, out);

    dim3 pgrid(256, 258);
    pack_kernel<<<pgrid, 64>>>(coeff3, coeff2, coeff1);

    dim3 grid(NROWS / BM, BATCH / BN);   // (260, 16)
    taylor_mma_kernel<<<grid, 256, SMEM_W * sizeof(float)>>>(out);
}